// round 10
// baseline (speedup 1.0000x reference)
#include <cuda_runtime.h>
#include <cuda_fp16.h>
#include <mma.h>
#include <math.h>
#include <stdint.h>

using namespace nvcuda;

// Problem constants
#define T_TOK 2048
#define H_DIM 1024
#define F_DIM 4096
#define E_NUM 4
#define CAP   2048

// GEMM tiling: 128x128 tile, BK=64 halves, 3-stage cp.async pipeline
#define BM 128
#define BN 128
#define BKH 64
#define LDA 72          // BKH + 8 pad (halves)
#define LDB 136         // BN + 8 pad (halves)
#define LDC 132         // floats, epilogue staging
#define NTHREADS 256
#define STAGES 3

#define STAGE_HALFS (BM * LDA + BKH * LDB)                      // 17920
#define SMEM_BYTES  (STAGES * STAGE_HALFS * (int)sizeof(__half)) // 107520

// gemm2 split-K
#define KSPLIT 2
#define KLEN   (F_DIM / KSPLIT)     // 2048
#define YP_OFF ((size_t)E_NUM * CAP * H_DIM)

// w2 convert chunking (float4 units)
#define W2_CHUNK4  4096
#define W2_NCHUNKS ((int)((size_t)E_NUM * F_DIM * H_DIM / 4 / W2_CHUNK4))  // 1024

// ---------------- scratch (static device globals; no allocation) ------------
__device__ __half g_xh[(size_t)T_TOK * H_DIM];
__device__ __half g_w1h[(size_t)E_NUM * H_DIM * F_DIM];
__device__ __half g_w2h[(size_t)E_NUM * F_DIM * H_DIM];
__device__ __half g_act[(size_t)E_NUM * CAP * F_DIM];
__device__ float  g_yp[2 * (size_t)E_NUM * CAP * H_DIM];   // split-K partials
__device__ int    g_cnt[E_NUM];
__device__ int    g_wq;
__device__ int    g_tok[E_NUM * CAP];
__device__ int    g_slot[T_TOK * E_NUM];

// ---------------- cp.async helpers ------------------------------------------
__device__ __forceinline__ void cp_async16(__half* smem_dst, const __half* gmem_src,
                                           bool pred) {
    unsigned int saddr = (unsigned int)__cvta_generic_to_shared(smem_dst);
    int sz = pred ? 16 : 0;   // src-size 0 -> zero-fill destination
    asm volatile("cp.async.cg.shared.global [%0], [%1], 16, %2;\n"
                 :: "r"(saddr), "l"(gmem_src), "r"(sz));
}
#define CP_COMMIT()  asm volatile("cp.async.commit_group;\n" ::)
#define CP_WAIT(n)   asm volatile("cp.async.wait_group %0;\n" :: "n"(n))

// ---------------- zero counters ----------------------------------------------
__global__ void zero_cnt_kernel() {
    if (threadIdx.x < E_NUM) g_cnt[threadIdx.x] = 0;
    if (threadIdx.x == E_NUM) g_wq = 0;
}

// ---------------- prep: route (blocks 0..7) + convert x,w1 (rest) -----------
__global__ void prep_kernel(const float* __restrict__ probs,
                            const float* __restrict__ x,
                            const float* __restrict__ w1)
{
    if (blockIdx.x < 8) {
        int t = blockIdx.x * blockDim.x + threadIdx.x;
        if (t >= T_TOK) return;
#pragma unroll
        for (int e = 0; e < E_NUM; e++) {
            float p = probs[t * E_NUM + e];
            if (p > 0.0f) {
                int pos = atomicAdd(&g_cnt[e], 1);
                g_tok[e * CAP + pos] = t;
                g_slot[t * E_NUM + e] = e * CAP + pos;
            }
        }
        return;
    }
    const size_t nx4 = (size_t)T_TOK * H_DIM / 4;          // 524288
    const size_t nw4 = (size_t)E_NUM * H_DIM * F_DIM / 4;  // 4194304
    size_t i = (size_t)(blockIdx.x - 8) * blockDim.x + threadIdx.x;
    size_t stride = (size_t)(gridDim.x - 8) * blockDim.x;
    for (; i < nx4 + nw4; i += stride) {
        if (i < nx4) {
            float4 v = reinterpret_cast<const float4*>(x)[i];
            reinterpret_cast<__half2*>(g_xh)[i * 2 + 0] = __floats2half2_rn(v.x, v.y);
            reinterpret_cast<__half2*>(g_xh)[i * 2 + 1] = __floats2half2_rn(v.z, v.w);
        } else {
            size_t j = i - nx4;
            float4 v = reinterpret_cast<const float4*>(w1)[j];
            reinterpret_cast<__half2*>(g_w1h)[j * 2 + 0] = __floats2half2_rn(v.x, v.y);
            reinterpret_cast<__half2*>(g_w1h)[j * 2 + 1] = __floats2half2_rn(v.z, v.w);
        }
    }
}

// ---------------- shared MMA core -------------------------------------------
// 8 warps: warp_m = w>>1 (4 rows of 32), warp_n = w&1 (2 cols of 64)
struct Frags {
    wmma::fragment<wmma::accumulator, 16, 16, 16, float> acc[2][4];
};

__device__ __forceinline__ void mma_stage(const __half* sA, const __half* sB,
                                          int warp_m, int warp_n, Frags& fr) {
#pragma unroll
    for (int kk = 0; kk < BKH; kk += 16) {
        wmma::fragment<wmma::matrix_a, 16, 16, 16, __half, wmma::row_major> a[2];
        wmma::fragment<wmma::matrix_b, 16, 16, 16, __half, wmma::row_major> b[4];
#pragma unroll
        for (int i = 0; i < 2; i++)
            wmma::load_matrix_sync(a[i], &sA[(warp_m * 32 + i * 16) * LDA + kk], LDA);
#pragma unroll
        for (int j = 0; j < 4; j++)
            wmma::load_matrix_sync(b[j], &sB[kk * LDB + warp_n * 64 + j * 16], LDB);
#pragma unroll
        for (int i = 0; i < 2; i++)
#pragma unroll
            for (int j = 0; j < 4; j++)
                wmma::mma_sync(fr.acc[i][j], a[i], b[j], fr.acc[i][j]);
    }
}

// ---------------- GEMM1: act = gelu( gather(Xh) @ w1h ); idle blocks convert w2
// grid: (F/BN=32, CAP/BM=16, E), block: 256
__global__ __launch_bounds__(NTHREADS, 2) void gemm1_kernel(
    const float* __restrict__ W2)
{
    extern __shared__ __align__(16) __half smem[];
    const int e   = blockIdx.z;
    const int cnt = g_cnt[e];
    const int m0  = blockIdx.y * BM;
    const int tid = threadIdx.x;

    if (m0 >= cnt) {
        // idle block: drain w2 fp32->fp16 chunk queue (overlaps active GEMM work)
        __shared__ int s_chunk;
        const float4* src = reinterpret_cast<const float4*>(W2);
        while (true) {
            if (tid == 0) s_chunk = atomicAdd(&g_wq, 1);
            __syncthreads();
            int c = s_chunk;
            __syncthreads();
            if (c >= W2_NCHUNKS) return;
            size_t base = (size_t)c * W2_CHUNK4;
#pragma unroll 4
            for (int j = tid; j < W2_CHUNK4; j += NTHREADS) {
                float4 v = src[base + j];
                __half2* d = reinterpret_cast<__half2*>(&g_w2h[(base + j) * 4]);
                d[0] = __floats2half2_rn(v.x, v.y);
                d[1] = __floats2half2_rn(v.z, v.w);
            }
        }
    }

    const int n0  = blockIdx.x * BN;
    const int w   = tid >> 5;
    const int warp_m = w >> 1;
    const int warp_n = w & 1;

    // A tile: 128 rows x 64 halves = 8 chunks(16B)/row, 1024 chunks, 4/thread
    int a_row[4], a_col[4], a_tok[4];
    bool a_ok[4];
#pragma unroll
    for (int i = 0; i < 4; i++) {
        int id = tid + i * NTHREADS;
        a_row[i] = id >> 3;
        a_col[i] = (id & 7) * 8;
        int m = m0 + a_row[i];
        a_ok[i] = (m < cnt);
        a_tok[i] = a_ok[i] ? __ldg(&g_tok[e * CAP + m]) : 0;
    }
    // B tile: 64 rows x 128 halves = 16 chunks/row, 1024 chunks, 4/thread
    int b_row[4], b_col[4];
#pragma unroll
    for (int i = 0; i < 4; i++) {
        int id = tid + i * NTHREADS;
        b_row[i] = id >> 4;
        b_col[i] = (id & 15) * 8;
    }

    const __half* W1e = &g_w1h[(size_t)e * H_DIM * F_DIM];

    Frags fr;
#pragma unroll
    for (int i = 0; i < 2; i++)
#pragma unroll
        for (int j = 0; j < 4; j++) wmma::fill_fragment(fr.acc[i][j], 0.0f);

    const int NK = H_DIM / BKH;   // 16

#pragma unroll
    for (int s = 0; s < STAGES - 1; s++) {
        __half* sA = smem + s * STAGE_HALFS;
        __half* sB = sA + BM * LDA;
        const int k0 = s * BKH;
#pragma unroll
        for (int i = 0; i < 4; i++)
            cp_async16(&sA[a_row[i] * LDA + a_col[i]],
                       &g_xh[(size_t)a_tok[i] * H_DIM + k0 + a_col[i]], a_ok[i]);
#pragma unroll
        for (int i = 0; i < 4; i++)
            cp_async16(&sB[b_row[i] * LDB + b_col[i]],
                       &W1e[(size_t)(k0 + b_row[i]) * F_DIM + n0 + b_col[i]], true);
        CP_COMMIT();
    }

    int buf = 0, nbuf = STAGES - 1;
    for (int kt = 0; kt < NK; kt++) {
        CP_WAIT(1);
        __syncthreads();
        if (kt + 2 < NK) {
            __half* sA = smem + nbuf * STAGE_HALFS;
            __half* sB = sA + BM * LDA;
            const int k0 = (kt + 2) * BKH;
#pragma unroll
            for (int i = 0; i < 4; i++)
                cp_async16(&sA[a_row[i] * LDA + a_col[i]],
                           &g_xh[(size_t)a_tok[i] * H_DIM + k0 + a_col[i]], a_ok[i]);
#pragma unroll
            for (int i = 0; i < 4; i++)
                cp_async16(&sB[b_row[i] * LDB + b_col[i]],
                           &W1e[(size_t)(k0 + b_row[i]) * F_DIM + n0 + b_col[i]], true);
        }
        CP_COMMIT();
        mma_stage(smem + buf * STAGE_HALFS,
                  smem + buf * STAGE_HALFS + BM * LDA, warp_m, warp_n, fr);
        buf  = (buf  == STAGES - 1) ? 0 : buf + 1;
        nbuf = (nbuf == STAGES - 1) ? 0 : nbuf + 1;
    }
    CP_WAIT(0);
    __syncthreads();

    // epilogue: stage C (float) in smem, gelu, convert to half, store
    float* sC = reinterpret_cast<float*>(smem);
#pragma unroll
    for (int i = 0; i < 2; i++)
#pragma unroll
        for (int j = 0; j < 4; j++)
            wmma::store_matrix_sync(
                &sC[(warp_m * 32 + i * 16) * LDC + warp_n * 64 + j * 16],
                fr.acc[i][j], LDC, wmma::mem_row_major);
    __syncthreads();
#pragma unroll
    for (int i = 0; i < 16; i++) {
        int id  = tid + i * NTHREADS;
        int row = id >> 5;
        int c   = (id & 31) * 4;
        int m   = m0 + row;
        if (m < cnt) {
            float4 v = *reinterpret_cast<const float4*>(&sC[row * LDC + c]);
            v.x = 0.5f * v.x * (1.0f + erff(v.x * 0.70710678118654752f));
            v.y = 0.5f * v.y * (1.0f + erff(v.y * 0.70710678118654752f));
            v.z = 0.5f * v.z * (1.0f + erff(v.z * 0.70710678118654752f));
            v.w = 0.5f * v.w * (1.0f + erff(v.w * 0.70710678118654752f));
            __half2* dst = reinterpret_cast<__half2*>(
                &g_act[(size_t)(e * CAP + m) * F_DIM + n0 + c]);
            dst[0] = __floats2half2_rn(v.x, v.y);
            dst[1] = __floats2half2_rn(v.z, v.w);
        }
    }
}

// ---------------- GEMM2: yp[half] = act_h[:, half] @ w2h[half] ---------------
// grid: (H/BN=8, CAP/BM=16, E*KSPLIT=8), block: 256
__global__ __launch_bounds__(NTHREADS, 2) void gemm2_kernel()
{
    extern __shared__ __align__(16) __half smem[];
    const int e    = blockIdx.z >> 1;
    const int half = blockIdx.z & 1;
    const int cnt  = g_cnt[e];
    const int m0   = blockIdx.y * BM;
    if (m0 >= cnt) return;
    const int n0   = blockIdx.x * BN;
    const int tid  = threadIdx.x;
    const int w    = tid >> 5;
    const int warp_m = w >> 1;
    const int warp_n = w & 1;
    const int kbase = half * KLEN;

    int a_row[4], a_col[4], b_row[4], b_col[4];
#pragma unroll
    for (int i = 0; i < 4; i++) {
        int id = tid + i * NTHREADS;
        a_row[i] = id >> 3;
        a_col[i] = (id & 7) * 8;
        b_row[i] = id >> 4;
        b_col[i] = (id & 15) * 8;
    }

    const __half* A   = &g_act[(size_t)(e * CAP) * F_DIM];  // stale rows>=cnt unread
    const __half* W2e = &g_w2h[(size_t)e * F_DIM * H_DIM];

    Frags fr;
#pragma unroll
    for (int i = 0; i < 2; i++)
#pragma unroll
        for (int j = 0; j < 4; j++) wmma::fill_fragment(fr.acc[i][j], 0.0f);

    const int NK = KLEN / BKH;   // 32

#pragma unroll
    for (int s = 0; s < STAGES - 1; s++) {
        __half* sA = smem + s * STAGE_HALFS;
        __half* sB = sA + BM * LDA;
        const int k0 = kbase + s * BKH;
#pragma unroll
        for (int i = 0; i < 4; i++)
            cp_async16(&sA[a_row[i] * LDA + a_col[i]],
                       &A[(size_t)(m0 + a_row[i]) * F_DIM + k0 + a_col[i]], true);
#pragma unroll
        for (int i = 0; i < 4; i++)
            cp_async16(&sB[b_row[i] * LDB + b_col[i]],
                       &W2e[(size_t)(k0 + b_row[i]) * H_DIM + n0 + b_col[i]], true);
        CP_COMMIT();
    }

    int buf = 0, nbuf = STAGES - 1;
    for (int kt = 0; kt < NK; kt++) {
        CP_WAIT(1);
        __syncthreads();
        if (kt + 2 < NK) {
            __half* sA = smem + nbuf * STAGE_HALFS;
            __half* sB = sA + BM * LDA;
            const int k0 = kbase + (kt + 2) * BKH;
#pragma unroll
            for (int i = 0; i < 4; i++)
                cp_async16(&sA[a_row[i] * LDA + a_col[i]],
                           &A[(size_t)(m0 + a_row[i]) * F_DIM + k0 + a_col[i]], true);
#pragma unroll
            for (int i = 0; i < 4; i++)
                cp_async16(&sB[b_row[i] * LDB + b_col[i]],
                           &W2e[(size_t)(k0 + b_row[i]) * H_DIM + n0 + b_col[i]], true);
        }
        CP_COMMIT();
        mma_stage(smem + buf * STAGE_HALFS,
                  smem + buf * STAGE_HALFS + BM * LDA, warp_m, warp_n, fr);
        buf  = (buf  == STAGES - 1) ? 0 : buf + 1;
        nbuf = (nbuf == STAGES - 1) ? 0 : nbuf + 1;
    }
    CP_WAIT(0);

    // epilogue: store accumulators to this half's partial buffer
    float* yp = g_yp + (size_t)half * YP_OFF;
#pragma unroll
    for (int i = 0; i < 2; i++)
#pragma unroll
        for (int j = 0; j < 4; j++)
            wmma::store_matrix_sync(
                &yp[(size_t)(e * CAP + m0 + warp_m * 32 + i * 16) * H_DIM
                    + n0 + warp_n * 64 + j * 16],
                fr.acc[i][j], H_DIM, wmma::mem_row_major);
}

// ---------------- combine: out = residual + sum_e p * (yp0 + yp1) -----------
__global__ void combine_kernel(const float* __restrict__ res,
                               const float* __restrict__ probs,
                               float* __restrict__ out)
{
    int t = blockIdx.x;
    int h = threadIdx.x * 4;
    float4 acc = *reinterpret_cast<const float4*>(&res[(size_t)t * H_DIM + h]);
#pragma unroll
    for (int e = 0; e < E_NUM; e++) {
        float p = probs[t * E_NUM + e];
        if (p > 0.0f) {
            int s = g_slot[t * E_NUM + e];
            float4 y0 = *reinterpret_cast<const float4*>(&g_yp[(size_t)s * H_DIM + h]);
            float4 y1 = *reinterpret_cast<const float4*>(
                &g_yp[YP_OFF + (size_t)s * H_DIM + h]);
            acc.x += p * (y0.x + y1.x);
            acc.y += p * (y0.y + y1.y);
            acc.z += p * (y0.z + y1.z);
            acc.w += p * (y0.w + y1.w);
        }
    }
    *reinterpret_cast<float4*>(&out[(size_t)t * H_DIM + h]) = acc;
}

// ---------------- launcher ---------------------------------------------------
extern "C" void kernel_launch(void* const* d_in, const int* in_sizes, int n_in,
                              void* d_out, int out_size)
{
    const float* x     = (const float*)d_in[0];
    const float* res   = (const float*)d_in[1];
    const float* probs = (const float*)d_in[2];
    const float* w1    = (const float*)d_in[4];
    const float* w2    = (const float*)d_in[5];
    float* out = (float*)d_out;

    (void)cudaFuncSetAttribute(gemm1_kernel,
                               cudaFuncAttributeMaxDynamicSharedMemorySize, SMEM_BYTES);
    (void)cudaFuncSetAttribute(gemm2_kernel,
                               cudaFuncAttributeMaxDynamicSharedMemorySize, SMEM_BYTES);

    zero_cnt_kernel<<<1, 32>>>();
    prep_kernel<<<8 + 1536, NTHREADS>>>(probs, x, w1);
    gemm1_kernel<<<dim3(F_DIM / BN, CAP / BM, E_NUM), NTHREADS, SMEM_BYTES>>>(w2);
    gemm2_kernel<<<dim3(H_DIM / BN, CAP / BM, E_NUM * KSPLIT), NTHREADS, SMEM_BYTES>>>();
    combine_kernel<<<T_TOK, 256>>>(res, probs, out);
}